// round 1
// baseline (speedup 1.0000x reference)
#include <cuda_runtime.h>

#define NT 256
#define ROWLEN 1024

// exp_int for one element, exactly mirroring the reference's fp32 op sequence.
__device__ __forceinline__ float int_exp1(float xi, float x0_int, float nx0,
                                          float b_int, float c_int)
{
    xi = fmaxf(xi, nx0);                       // jnp.maximum(x_int, n*x0_int)
    float q = floorf(__fdiv_rn(xi, x0_int));   // floor(x_int / x0_int), q in [0,15]
    float r = xi - __fmul_rn(x0_int, q);       // x0_int*q is an exact small integer
    float z = __fmaf_rn(r, __fadd_rn(r, b_int), c_int);  // r*(r+b_int)+c_int
    int qi = (int)q;                           // exact: q is an integer in [0,15]
    float p = __int_as_float((142 - qi) << 23);  // 2^(15-q), exact power of two
    return fmaxf(floorf(__fmul_rn(z, p)), 0.0f);
}

__global__ __launch_bounds__(NT)
void qsisoftmax_kernel(const float* __restrict__ x,
                       const float* __restrict__ scale_p,
                       const float* __restrict__ thr_p,
                       float* __restrict__ out)
{
    __shared__ float sh[NT / 32];
    __shared__ float sbc;

    const int t = threadIdx.x;
    const size_t base = (size_t)blockIdx.x * ROWLEN;

    // One float4 per thread: the whole row lives in registers.
    float4 v = reinterpret_cast<const float4*>(x + base)[t];

    const float sf  = __ldg(scale_p);
    const float thr = __ldg(thr_p);

    // Constants: python-float64 ratios rounded to fp32 at the op boundary
    // (matches JAX weak-type promotion), then fp32 divide + floor.
    const float r1 = (float)(0.96963238 / 0.35815147);   // c1/c0
    const float r2 = (float)(1.0 / 0.35815147);          // c2/c0
    const float b_int  = floorf(__fdiv_rn(r1, sf));
    const float c_int  = floorf(__fdiv_rn(r2, __fmul_rn(sf, sf)));
    const float x0_int = floorf(__fdiv_rn(-0.69314718f, sf));
    const float nx0    = __fmul_rn(15.0f, x0_int);       // n * x0_int

    // x_int = x / sf  (element-wise fp32 division, as in reference)
    float xi0 = __fdiv_rn(v.x, sf);
    float xi1 = __fdiv_rn(v.y, sf);
    float xi2 = __fdiv_rn(v.z, sf);
    float xi3 = __fdiv_rn(v.w, sf);

    // ---- block max over the row ----
    float m = fmaxf(fmaxf(xi0, xi1), fmaxf(xi2, xi3));
    #pragma unroll
    for (int o = 16; o; o >>= 1)
        m = fmaxf(m, __shfl_xor_sync(0xffffffffu, m, o));
    if ((t & 31) == 0) sh[t >> 5] = m;
    __syncthreads();
    if (t == 0) {
        float mm = sh[0];
        #pragma unroll
        for (int i = 1; i < NT / 32; i++) mm = fmaxf(mm, sh[i]);
        sbc = mm;
    }
    __syncthreads();
    const float rmax = sbc;

    // ---- int_exp per element (kept in registers) ----
    float e0 = int_exp1(xi0 - rmax, x0_int, nx0, b_int, c_int);
    float e1 = int_exp1(xi1 - rmax, x0_int, nx0, b_int, c_int);
    float e2 = int_exp1(xi2 - rmax, x0_int, nx0, b_int, c_int);
    float e3 = int_exp1(xi3 - rmax, x0_int, nx0, b_int, c_int);

    // ---- block sum of exp_int ----
    float s = ((e0 + e1) + (e2 + e3));
    #pragma unroll
    for (int o = 16; o; o >>= 1)
        s += __shfl_xor_sync(0xffffffffu, s, o);
    if ((t & 31) == 0) sh[t >> 5] = s;
    __syncthreads();
    if (t == 0) {
        float ss = sh[0];
        #pragma unroll
        for (int i = 1; i < NT / 32; i++) ss += sh[i];
        sbc = ss;
    }
    __syncthreads();
    const float ssum = sbc;

    // ---- row-level quantization constants ----
    const float factor = floorf(__fdiv_rn(4294967296.0f, ssum));
    // approx_threshold = floor(thr * 2^8) * sum / 2^8
    const float approx = __fdiv_rn(__fmul_rn(floorf(__fmul_rn(thr, 256.0f)), ssum), 256.0f);
    const float osA = __fdiv_rn(thr, 255.0f);            // threshold / 255 (fp32)
    const float dA  = __fmul_rn(4294967296.0f, osA);     // 2^32 * out_scale_A (fp32)
    const float dB  = (float)(4294967296.0 / 255.0);     // fp32(2^32 * (1/255)), f64 then cast
    const float osB = (float)(1.0 / 255.0);

    // ---- quantized split output ----
    float4 o;
    {
        float ef = __fmul_rn(e0, factor);
        o.x = (e0 <= approx) ? __fmul_rn(floorf(__fdiv_rn(ef, dA)), osA)
                             : __fmul_rn(fminf(floorf(__fdiv_rn(ef, dB)), 255.0f), osB);
    }
    {
        float ef = __fmul_rn(e1, factor);
        o.y = (e1 <= approx) ? __fmul_rn(floorf(__fdiv_rn(ef, dA)), osA)
                             : __fmul_rn(fminf(floorf(__fdiv_rn(ef, dB)), 255.0f), osB);
    }
    {
        float ef = __fmul_rn(e2, factor);
        o.z = (e2 <= approx) ? __fmul_rn(floorf(__fdiv_rn(ef, dA)), osA)
                             : __fmul_rn(fminf(floorf(__fdiv_rn(ef, dB)), 255.0f), osB);
    }
    {
        float ef = __fmul_rn(e3, factor);
        o.w = (e3 <= approx) ? __fmul_rn(floorf(__fdiv_rn(ef, dA)), osA)
                             : __fmul_rn(fminf(floorf(__fdiv_rn(ef, dB)), 255.0f), osB);
    }

    reinterpret_cast<float4*>(out + base)[t] = o;
}

extern "C" void kernel_launch(void* const* d_in, const int* in_sizes, int n_in,
                              void* d_out, int out_size)
{
    const float* x     = (const float*)d_in[0];
    const float* scale = (const float*)d_in[1];
    const float* thr   = (const float*)d_in[2];
    float* out = (float*)d_out;

    int rows = out_size / ROWLEN;   // 32768 for (2,16,1024,1024)
    qsisoftmax_kernel<<<rows, NT>>>(x, scale, thr, out);
}

// round 2
// speedup vs baseline: 2.1505x; 2.1505x over previous
#include <cuda_runtime.h>

#define NT 128
#define ROWLEN 1024
#define NW (NT / 32)

__global__ __launch_bounds__(NT)
void qsisoftmax_kernel(const float* __restrict__ x,
                       const float* __restrict__ scale_p,
                       const float* __restrict__ thr_p,
                       float* __restrict__ out)
{
    __shared__ float shm[NW], shs[NW];

    const int t = threadIdx.x;
    const size_t base = (size_t)blockIdx.x * ROWLEN;
    const float4* __restrict__ xin = reinterpret_cast<const float4*>(x + base);

    // 8 elements per thread, two coalesced float4 loads (MLP=2 front-batched).
    float4 v0 = xin[t];
    float4 v1 = xin[t + NT];

    const float sf  = __ldg(scale_p);
    const float thr = __ldg(thr_p);

    // One-time reciprocals / constants (MUFU.RCP, amortized over 8 elems).
    const float rs = __frcp_rn(sf);                       // 1/sf
    const float r1c = (float)(0.96963238 / 0.35815147);   // c1/c0 (f64 → f32)
    const float r2c = (float)(1.0 / 0.35815147);          // c2/c0
    const float b_int  = floorf(__fmul_rn(r1c, rs));
    const float c_int  = floorf(__fmul_rn(__fmul_rn(r2c, rs), rs));
    const float x0_int = floorf(__fmul_rn(-0.69314718f, rs));
    const float nx0    = __fmul_rn(15.0f, x0_int);        // n * x0_int
    const float inv_x0 = __frcp_rn(x0_int);

    // x_int = x * (1/sf)  — replaces per-element correctly-rounded divide.
    float xi[8];
    xi[0] = __fmul_rn(v0.x, rs); xi[1] = __fmul_rn(v0.y, rs);
    xi[2] = __fmul_rn(v0.z, rs); xi[3] = __fmul_rn(v0.w, rs);
    xi[4] = __fmul_rn(v1.x, rs); xi[5] = __fmul_rn(v1.y, rs);
    xi[6] = __fmul_rn(v1.z, rs); xi[7] = __fmul_rn(v1.w, rs);

    // ---- block max ----
    float m = xi[0];
    #pragma unroll
    for (int i = 1; i < 8; i++) m = fmaxf(m, xi[i]);
    #pragma unroll
    for (int o = 16; o; o >>= 1) m = fmaxf(m, __shfl_xor_sync(0xffffffffu, m, o));
    if ((t & 31) == 0) shm[t >> 5] = m;
    __syncthreads();
    m = fmaxf(fmaxf(shm[0], shm[1]), fmaxf(shm[2], shm[3]));

    // ---- int_exp per element (registers) + local sum ----
    float e[8];
    float s = 0.0f;
    #pragma unroll
    for (int i = 0; i < 8; i++) {
        float d  = fmaxf(xi[i] - m, nx0);                  // clamp to n*x0_int
        float qf = floorf(__fmul_rn(d, inv_x0));           // q = floor(d / x0_int)
        float r  = __fmaf_rn(-x0_int, qf, d);              // d - x0_int*q (x0*q exact)
        float z  = __fmaf_rn(r, __fadd_rn(r, b_int), c_int);
        int   qi = (int)qf;                                // q in [0,15]
        float p  = __int_as_float(0x47000000 - (qi << 23)); // exact 2^(15-q)
        float ev = fmaxf(floorf(__fmul_rn(z, p)), 0.0f);
        e[i] = ev;
        s += ev;
    }

    // ---- block sum ----
    #pragma unroll
    for (int o = 16; o; o >>= 1) s += __shfl_xor_sync(0xffffffffu, s, o);
    if ((t & 31) == 0) shs[t >> 5] = s;
    __syncthreads();
    s = (shs[0] + shs[1]) + (shs[2] + shs[3]);

    // ---- row-level quantization constants (once per thread) ----
    const float factor = floorf(__fmul_rn(4294967296.0f, __frcp_rn(s)));
    const float thr_i  = floorf(__fmul_rn(thr, 256.0f));
    const float approx = __fmul_rn(__fmul_rn(thr_i, s), 0.00390625f); // /256 exact
    const float osA    = __fdiv_rn(thr, 255.0f);          // matches ref rounding
    const float osB    = (float)(1.0 / 255.0);
    const float invdA  = __frcp_rn(__fmul_rn(4294967296.0f, osA));
    const float invdB  = __frcp_rn((float)(4294967296.0 / 255.0));
    const float INF    = __int_as_float(0x7f800000);

    // ---- quantized split output ----
    float o8[8];
    #pragma unroll
    for (int i = 0; i < 8; i++) {
        bool  A    = (e[i] <= approx);
        float ef   = __fmul_rn(e[i], factor);
        float invd = A ? invdA : invdB;
        float osc  = A ? osA   : osB;
        float clmp = A ? INF   : 255.0f;
        float qv   = fminf(floorf(__fmul_rn(ef, invd)), clmp);
        o8[i] = __fmul_rn(qv, osc);
    }

    float4* __restrict__ oo = reinterpret_cast<float4*>(out + base);
    oo[t]      = make_float4(o8[0], o8[1], o8[2], o8[3]);
    oo[t + NT] = make_float4(o8[4], o8[5], o8[6], o8[7]);
}

extern "C" void kernel_launch(void* const* d_in, const int* in_sizes, int n_in,
                              void* d_out, int out_size)
{
    const float* x     = (const float*)d_in[0];
    const float* scale = (const float*)d_in[1];
    const float* thr   = (const float*)d_in[2];
    float* out = (float*)d_out;

    int rows = out_size / ROWLEN;   // 32768 for (2,16,1024,1024)
    qsisoftmax_kernel<<<rows, NT>>>(x, scale, thr, out);
}

// round 6
// speedup vs baseline: 2.2737x; 1.0573x over previous
#include <cuda_runtime.h>

#define NT 128
#define ROWLEN 1024
#define NW (NT / 32)

// Order-preserving float->u32 bijection (works for all finite floats).
__device__ __forceinline__ unsigned f2ord(float f) {
    int i = __float_as_int(f);
    return (unsigned)(i ^ ((i >> 31) | 0x80000000));
}
__device__ __forceinline__ float ord2f(unsigned k) {
    int m = (~((int)k >> 31)) | 0x80000000;
    return __int_as_float((int)(k ^ (unsigned)m));
}
__device__ __forceinline__ unsigned warp_max_u32(unsigned v) {
    unsigned r;
    asm volatile("redux.sync.max.u32 %0, %1, 0xffffffff;" : "=r"(r) : "r"(v));
    return r;
}

__global__ __launch_bounds__(NT)
void qsisoftmax_kernel(const float* __restrict__ x,
                       const float* __restrict__ scale_p,
                       const float* __restrict__ thr_p,
                       float* __restrict__ out)
{
    __shared__ unsigned shm[NW];
    __shared__ float shs[NW];

    const int t = threadIdx.x;
    const size_t base = (size_t)blockIdx.x * ROWLEN;
    const float4* __restrict__ xin = reinterpret_cast<const float4*>(x + base);

    // 8 elements per thread, two streaming float4 loads (no reuse -> evict-first).
    float4 v0 = __ldcs(xin + t);
    float4 v1 = __ldcs(xin + t + NT);

    const float sf  = __ldg(scale_p);
    const float thr = __ldg(thr_p);

    // One-time constants (amortized over 8 elems).
    const float rs = __frcp_rn(sf);                       // 1/sf
    const float b_int  = floorf(__fmul_rn((float)(0.96963238 / 0.35815147), rs));
    const float c_int  = floorf(__fmul_rn(__fmul_rn((float)(1.0 / 0.35815147), rs), rs));
    const float x0_int = floorf(__fmul_rn(-0.69314718f, rs));
    const float nx0    = __fmul_rn(15.0f, x0_int);        // n * x0_int
    const float inv_x0 = __frcp_rn(x0_int);

    // x_int = x * (1/sf)
    float xi[8];
    xi[0] = __fmul_rn(v0.x, rs); xi[1] = __fmul_rn(v0.y, rs);
    xi[2] = __fmul_rn(v0.z, rs); xi[3] = __fmul_rn(v0.w, rs);
    xi[4] = __fmul_rn(v1.x, rs); xi[5] = __fmul_rn(v1.y, rs);
    xi[6] = __fmul_rn(v1.z, rs); xi[7] = __fmul_rn(v1.w, rs);

    // ---- block max: local fmax tree -> u32 redux -> cross-warp umax ----
    float lm = xi[0];
    #pragma unroll
    for (int i = 1; i < 8; i++) lm = fmaxf(lm, xi[i]);
    unsigned km = warp_max_u32(f2ord(lm));
    if ((t & 31) == 0) shm[t >> 5] = km;
    __syncthreads();
    km = max(max(shm[0], shm[1]), max(shm[2], shm[3]));
    const float m = ord2f(km);

    // ---- int_exp per element (registers) + local sum ----
    float e[8];
    float s = 0.0f;
    #pragma unroll
    for (int i = 0; i < 8; i++) {
        float d  = fmaxf(xi[i] - m, nx0);                  // clamp to n*x0_int
        float qf = floorf(__fmul_rn(d, inv_x0));           // q in [0,15]
        float r  = __fmaf_rn(-x0_int, qf, d);              // d - x0_int*q
        float z  = __fmaf_rn(r, __fadd_rn(r, b_int), c_int); // > 0 (disc < 0)
        int   qi = (int)qf;
        float p  = __int_as_float(0x47000000 - (qi << 23)); // exact 2^(15-q)
        float ev = floorf(__fmul_rn(z, p));                // >= 0, clamp dead
        e[i] = ev;
        s += ev;
    }

    // ---- block sum: shfl butterfly (fp32; u32 would overflow) ----
    #pragma unroll
    for (int o = 16; o; o >>= 1) s += __shfl_xor_sync(0xffffffffu, s, o);
    if ((t & 31) == 0) shs[t >> 5] = s;
    __syncthreads();
    s = (shs[0] + shs[1]) + (shs[2] + shs[3]);

    // ---- row-level quantization constants ----
    const float factor = floorf(__fmul_rn(4294967296.0f, __frcp_rn(s)));
    const float approx = __fmul_rn(__fmul_rn(floorf(__fmul_rn(thr, 256.0f)), s),
                                   0.00390625f);           // /256 exact
    const float osA = __fmul_rn(thr, (float)(1.0 / 255.0));
    const float osB = (float)(1.0 / 255.0);
    // folded per-row multipliers: floor(e * g) == floor(e*factor/denom) up to ulps
    const float gA = __fmul_rn(factor, __frcp_rn(__fmul_rn(4294967296.0f, osA)));
    const float gB = __fmul_rn(factor, (float)(255.0 / 4294967296.0));
    const float INF = __int_as_float(0x7f800000);

    // ---- quantized split output ----
    float o8[8];
    #pragma unroll
    for (int i = 0; i < 8; i++) {
        bool  A    = (e[i] <= approx);
        float g    = A ? gA  : gB;
        float clmp = A ? INF : 255.0f;
        float osc  = A ? osA : osB;
        float qv   = fminf(floorf(__fmul_rn(e[i], g)), clmp);
        o8[i] = __fmul_rn(qv, osc);
    }

    float4* __restrict__ oo = reinterpret_cast<float4*>(out + base);
    __stcs(oo + t,      make_float4(o8[0], o8[1], o8[2], o8[3]));
    __stcs(oo + t + NT, make_float4(o8[4], o8[5], o8[6], o8[7]));
}

extern "C" void kernel_launch(void* const* d_in, const int* in_sizes, int n_in,
                              void* d_out, int out_size)
{
    const float* x     = (const float*)d_in[0];
    const float* scale = (const float*)d_in[1];
    const float* thr   = (const float*)d_in[2];
    float* out = (float*)d_out;

    int rows = out_size / ROWLEN;   // 32768 for (2,16,1024,1024)
    qsisoftmax_kernel<<<rows, NT>>>(x, scale, thr, out);
}